// round 16
// baseline (speedup 1.0000x reference)
#include <cuda_runtime.h>
#include <cuda_bf16.h>
#include <math.h>
#include <stdint.h>

#define DIM   512
#define NH    8
#define HD    64
#define SEQ   2048
#define BATCH 2
#define MTOT  (BATCH * SEQ)   // 4096
#define KIN   (2 * DIM)       // 1024

typedef unsigned long long u64t;

// ---- packed f32x2 helpers ----
__device__ __forceinline__ u64t fma2(u64t a, u64t b, u64t c) {
    u64t d; asm("fma.rn.f32x2 %0, %1, %2, %3;" : "=l"(d) : "l"(a), "l"(b), "l"(c));
    return d;
}
__device__ __forceinline__ u64t mul2(u64t a, u64t b) {
    u64t d; asm("mul.rn.f32x2 %0, %1, %2;" : "=l"(d) : "l"(a), "l"(b));
    return d;
}
__device__ __forceinline__ u64t dup2f(float x) {
    u64t r; asm("mov.b64 %0, {%1, %1};" : "=l"(r) : "f"(x));
    return r;
}
__device__ __forceinline__ u64t pk2(float a, float b) {
    u64t r; asm("mov.b64 %0, {%1, %2};" : "=l"(r) : "f"(a), "f"(b));
    return r;
}
__device__ __forceinline__ float2 unpk(u64t v) {
    float lo, hi; asm("mov.b64 {%0, %1}, %2;" : "=f"(lo), "=f"(hi) : "l"(v));
    float2 f; f.x = lo; f.y = hi; return f;
}

// ---- bf16x2 split (bit-trick, rounding identical to __float2bfloat16) ----
__device__ __forceinline__ void split2(float x, float y, uint32_t& hi, uint32_t& lo) {
    uint32_t h;
    asm("cvt.rn.bf16x2.f32 %0, %1, %2;" : "=r"(h) : "f"(y), "f"(x));
    float hx = __uint_as_float(h << 16);
    float hy = __uint_as_float(h & 0xffff0000u);
    float rx = x - hx;
    float ry = y - hy;
    asm("cvt.rn.bf16x2.f32 %0, %1, %2;" : "=r"(lo) : "f"(ry), "f"(rx));
    hi = h;
}

// ---- mma.sync m16n8k16 bf16 ----
__device__ __forceinline__ void mma_bf16(float c[4], const uint32_t a[4],
                                         uint32_t b0, uint32_t b1) {
    asm volatile(
        "mma.sync.aligned.m16n8k16.row.col.f32.bf16.bf16.f32 "
        "{%0,%1,%2,%3}, {%4,%5,%6,%7}, {%8,%9}, {%0,%1,%2,%3};"
        : "+f"(c[0]), "+f"(c[1]), "+f"(c[2]), "+f"(c[3])
        : "r"(a[0]), "r"(a[1]), "r"(a[2]), "r"(a[3]), "r"(b0), "r"(b1));
}
__device__ __forceinline__ void mma_bf16_u4(float c[4], uint4 a,
                                            uint32_t b0, uint32_t b1) {
    uint32_t ar[4] = { a.x, a.y, a.z, a.w };
    mma_bf16(c, ar, b0, b1);
}

// ---- cp.async 16B ----
__device__ __forceinline__ void cp16(void* smem_dst, const void* gsrc) {
    uint32_t s = (uint32_t)__cvta_generic_to_shared(smem_dst);
    asm volatile("cp.async.cg.shared.global [%0], [%1], 16;" :: "r"(s), "l"(gsrc));
}
#define CP_COMMIT() asm volatile("cp.async.commit_group;")
#define CP_WAIT0()  asm volatile("cp.async.wait_group 0;" ::: "memory")
#define CP_WAIT1()  asm volatile("cp.async.wait_group 1;" ::: "memory")

// ---------------------------------------------------------------------------
// Pre-split fragment-order global buffers
// ---------------------------------------------------------------------------
__device__ uint32_t g_XA[256 * 64 * 2 * 128];
__device__ uint32_t g_WqF[64 * 64 * 128];
__device__ uint32_t g_WkF[64 * 64 * 128];
__device__ uint32_t g_WvF[64 * 64 * 128];
__device__ uint32_t g_WoF[128 * 32 * 128];
__device__ uint32_t g_QA[16 * 128 * 4 * 2 * 128];
__device__ uint32_t g_KF[16 * 32 * 8 * 4 * 128];
__device__ uint32_t g_VF[16 * 32 * 8 * 4 * 128];
__device__ float    g_V [16 * SEQ * HD];
__device__ uint32_t g_AF[256 * 32 * 2 * 128];

// ---------------------------------------------------------------------------
// Prep: x -> A-frag split.  grid(32, 64), 256 thr.
// ---------------------------------------------------------------------------
__global__ __launch_bounds__(256) void prep_xa(
    const float* __restrict__ xr, const float* __restrict__ xi)
{
    const int lane = threadIdx.x & 31;
    const int warp = threadIdx.x >> 5;
    const int g = lane >> 2, tg = lane & 3;
    const int mg = blockIdx.x * 8 + warp;
    const int kg = blockIdx.y;
    const int m = mg * 16 + g;
    const int k = kg * 16 + 2 * tg;
    const float* base = (k < DIM) ? xr : xi;
    const int kk = k & (DIM - 1);
    float2 f00 = *(const float2*)(base + (size_t)m * DIM + kk);
    float2 f01 = *(const float2*)(base + (size_t)m * DIM + kk + 8);
    float2 f10 = *(const float2*)(base + (size_t)(m + 8) * DIM + kk);
    float2 f11 = *(const float2*)(base + (size_t)(m + 8) * DIM + kk + 8);
    uint32_t h[4], l[4];
    split2(f00.x, f00.y, h[0], l[0]);
    split2(f10.x, f10.y, h[1], l[1]);
    split2(f01.x, f01.y, h[2], l[2]);
    split2(f11.x, f11.y, h[3], l[3]);
    uint32_t* dst = g_XA + ((size_t)(mg * 64 + kg) * 2) * 128 + lane * 4;
    *(uint4*)dst         = make_uint4(h[0], h[1], h[2], h[3]);
    *(uint4*)(dst + 128) = make_uint4(l[0], l[1], l[2], l[3]);
}

// ---------------------------------------------------------------------------
// Prep: all four W -> B-frag split. grid(64, 8, 4), 256 thr.
// ---------------------------------------------------------------------------
__global__ __launch_bounds__(256) void prep_w_all(
    const float* __restrict__ Wq, const float* __restrict__ Wk,
    const float* __restrict__ Wv, const float* __restrict__ Wo)
{
    const int lane = threadIdx.x & 31;
    const int warp = threadIdx.x >> 5;
    const int g = lane >> 2, tg = lane & 3;
    const int z = blockIdx.z;

    int ng, ks, N, KGC;
    const float* W;
    uint32_t* WF;
    if (z < 3) {
        ng = blockIdx.x;
        ks = blockIdx.y * 8 + warp;
        N = DIM; KGC = 64;
        W  = (z == 0) ? Wq : (z == 1) ? Wk : Wv;
        WF = (z == 0) ? g_WqF : (z == 1) ? g_WkF : g_WvF;
    } else {
        const int id = blockIdx.y * 64 + blockIdx.x;
        ng = id >> 2;
        ks = (id & 3) * 8 + warp;
        N = KIN; KGC = 32;
        W = Wo; WF = g_WoF;
    }

    const int k = ks * 16 + 2 * tg;
    const int n = ng * 8 + g;
    float b0a = W[(size_t)k * N + n];
    float b0b = W[(size_t)(k + 1) * N + n];
    float b1a = W[(size_t)(k + 8) * N + n];
    float b1b = W[(size_t)(k + 9) * N + n];
    uint32_t h0, l0, h1, l1;
    split2(b0a, b0b, h0, l0);
    split2(b1a, b1b, h1, l1);
    *(uint4*)(WF + (size_t)(ng * KGC + ks) * 128 + lane * 4) = make_uint4(h0, h1, l0, l1);
}

// ---------------------------------------------------------------------------
// Repack V fp32 -> B-frag split.  grid(32 jt, 16 bh), 256 thr.
// ---------------------------------------------------------------------------
__global__ __launch_bounds__(256) void repack_v()
{
    const int lane = threadIdx.x & 31;
    const int dg = threadIdx.x >> 5;
    const int r = lane >> 2, cq = lane & 3;
    const int jt = blockIdx.x, bh = blockIdx.y;
    const float* Vb = g_V + (size_t)bh * SEQ * HD;
    const int j0 = jt * 64;
#pragma unroll
    for (int js = 0; js < 4; js++) {
        const float* vsrc = Vb + (size_t)(j0 + js * 16 + 2 * cq) * HD + dg * 8 + r;
        float v0 = vsrc[0];
        float v1 = vsrc[HD];
        float v2 = vsrc[8 * HD];
        float v3 = vsrc[9 * HD];
        uint32_t h0, l0, h1, l1;
        split2(v0, v1, h0, l0);
        split2(v2, v3, h1, l1);
        *(uint4*)(g_VF + ((size_t)((bh * 32 + jt) * 8 + dg) * 4 + js) * 128 + lane * 4)
            = make_uint4(h0, h1, l0, l1);
    }
}

// ---------------------------------------------------------------------------
// GEMM core: 3-stage cp.async pipeline (R13/R14 known-good).
// ---------------------------------------------------------------------------
template<int KGC>
__device__ __forceinline__ void gemm_core(
    const uint32_t* __restrict__ XA, const uint32_t* __restrict__ WF,
    float C[2][8][4])
{
    extern __shared__ uint32_t sm[];
    uint32_t* AsmB = sm;             // [3][8][2][256]
    uint32_t* BsmB = sm + 12288;     // [3][16][2][128]

    const int tid  = threadIdx.x;
    const int warp = tid >> 5;
    const int lane = tid & 31;
    const int wm = warp >> 1, wn = warp & 1;
    const int m0 = blockIdx.y * 128;
    const int n0 = blockIdx.x * 128;
    const int mgA = (m0 >> 4) + warp;
    const int ngB = (n0 >> 3);

    auto copy_chunk = [&](int ch, int bf) {
        const int kg0 = ch * 2;
        uint32_t* A = AsmB + bf * 4096;
        uint32_t* B = BsmB + bf * 4096;
#pragma unroll
        for (int t = 0; t < 2; t++) {
            const uint32_t* src = XA + ((size_t)(mgA * KGC + kg0 + t) * 2) * 128 + lane * 4;
            cp16(&A[warp * 512 + t * 256 + lane * 4], src);
            cp16(&A[warp * 512 + t * 256 + 128 + lane * 4], src + 128);
        }
#pragma unroll
        for (int t = 0; t < 4; t++) {
            const int ngl = warp * 2 + (t >> 1), ks = t & 1;
            cp16(&B[ngl * 256 + ks * 128 + lane * 4],
                 WF + (size_t)((ngB + ngl) * KGC + kg0 + ks) * 128 + lane * 4);
        }
        CP_COMMIT();
    };

#pragma unroll
    for (int mg = 0; mg < 2; mg++)
#pragma unroll
        for (int ng = 0; ng < 8; ng++)
#pragma unroll
            for (int e = 0; e < 4; e++) C[mg][ng][e] = 0.0f;

    const int NCH = KGC / 2;
    copy_chunk(0, 0);
    copy_chunk(1, 1);

    for (int ch = 0; ch < NCH; ++ch) {
        const int cur = ch % 3;
        if (ch + 1 < NCH) { CP_WAIT1(); } else { CP_WAIT0(); }
        __syncthreads();
        const uint32_t* A = AsmB + cur * 4096;
        const uint32_t* B = BsmB + cur * 4096;
#pragma unroll
        for (int ks = 0; ks < 2; ks++) {
            uint4 a0h = *(const uint4*)&A[(wm * 2 + 0) * 512 + ks * 256 + lane * 4];
            uint4 a0l = *(const uint4*)&A[(wm * 2 + 0) * 512 + ks * 256 + 128 + lane * 4];
            uint4 a1h = *(const uint4*)&A[(wm * 2 + 1) * 512 + ks * 256 + lane * 4];
            uint4 a1l = *(const uint4*)&A[(wm * 2 + 1) * 512 + ks * 256 + 128 + lane * 4];
#pragma unroll
            for (int ng = 0; ng < 8; ng++) {
                uint4 b = *(const uint4*)&B[(wn * 8 + ng) * 256 + ks * 128 + lane * 4];
                mma_bf16_u4(C[0][ng], a0h, b.x, b.y);
                mma_bf16_u4(C[0][ng], a0l, b.x, b.y);
                mma_bf16_u4(C[0][ng], a0h, b.z, b.w);
                mma_bf16_u4(C[1][ng], a1h, b.x, b.y);
                mma_bf16_u4(C[1][ng], a1l, b.x, b.y);
                mma_bf16_u4(C[1][ng], a1h, b.z, b.w);
            }
        }
        if (ch + 2 < NCH) copy_chunk(ch + 2, (ch + 2) % 3);
    }
}

// ---------------------------------------------------------------------------
// Fused Q/K/V projection (R14 known-good).
// ---------------------------------------------------------------------------
__global__ __launch_bounds__(256, 2) void proj_qkv(
    const float* __restrict__ bq, const float* __restrict__ bk,
    const float* __restrict__ bv)
{
    const int z = blockIdx.z;
    const uint32_t* WF = (z == 0) ? g_WqF : (z == 1) ? g_WkF : g_WvF;
    const float* bias = (z == 0) ? bq : (z == 1) ? bk : bv;

    float C[2][8][4];
    gemm_core<64>(g_XA, WF, C);

    const int tid  = threadIdx.x;
    const int warp = tid >> 5;
    const int lane = tid & 31;
    const int wm = warp >> 1, wn = warp & 1;
    const int g = lane >> 2, tg = lane & 3;
    const int m0 = blockIdx.y * 128;
    const int n0 = blockIdx.x * 128;
    const int h = (n0 + wn * 64) >> 6;

    float bb[8][2];
#pragma unroll
    for (int ng = 0; ng < 8; ng++) {
        const int n = n0 + wn * 64 + ng * 8 + 2 * tg;
        bb[ng][0] = bias[n];
        bb[ng][1] = bias[n + 1];
    }

#pragma unroll
    for (int mg = 0; mg < 2; mg++) {
        const int mtile = m0 + wm * 32 + mg * 16;
        const int b = mtile >> 11;
        const int stile = mtile & (SEQ - 1);
        const int bh = b * NH + h;
        float v[2][16];
#pragma unroll
        for (int half = 0; half < 2; half++) {
#pragma unroll
            for (int ng = 0; ng < 8; ng++) {
                v[half][2 * ng]     = C[mg][ng][half * 2]     + bb[ng][0];
                v[half][2 * ng + 1] = C[mg][ng][half * 2 + 1] + bb[ng][1];
            }
            if (z < 2) {
                float mx = v[half][0];
#pragma unroll
                for (int e = 1; e < 16; e++) mx = fmaxf(mx, v[half][e]);
                mx = fmaxf(mx, __shfl_xor_sync(0xffffffffu, mx, 1));
                mx = fmaxf(mx, __shfl_xor_sync(0xffffffffu, mx, 2));
                float sum = 0.0f;
#pragma unroll
                for (int e = 0; e < 16; e++) { v[half][e] = __expf(v[half][e] - mx); sum += v[half][e]; }
                sum += __shfl_xor_sync(0xffffffffu, sum, 1);
                sum += __shfl_xor_sync(0xffffffffu, sum, 2);
                const float inv = 1.0f / sum;
#pragma unroll
                for (int e = 0; e < 16; e++) v[half][e] = sqrtf(v[half][e] * inv);
            }
        }

        if (z == 0) {
            const int sg = stile >> 4;
#pragma unroll
            for (int ks = 0; ks < 4; ks++) {
                uint32_t h4[4], l4[4];
                split2(v[0][4 * ks],     v[0][4 * ks + 1], h4[0], l4[0]);
                split2(v[1][4 * ks],     v[1][4 * ks + 1], h4[1], l4[1]);
                split2(v[0][4 * ks + 2], v[0][4 * ks + 3], h4[2], l4[2]);
                split2(v[1][4 * ks + 2], v[1][4 * ks + 3], h4[3], l4[3]);
                uint32_t* dst = g_QA + (((size_t)(bh * 128 + sg) * 4 + ks) * 2) * 128 + lane * 4;
                *(uint4*)dst         = make_uint4(h4[0], h4[1], h4[2], h4[3]);
                *(uint4*)(dst + 128) = make_uint4(l4[0], l4[1], l4[2], l4[3]);
            }
        } else if (z == 1) {
#pragma unroll
            for (int half = 0; half < 2; half++) {
                const int s = stile + g + half * 8;
                const int jt = s >> 6, jg = (s >> 3) & 7;
                const int lp = (s & 7) * 4 + tg;
#pragma unroll
                for (int ks = 0; ks < 4; ks++) {
                    uint32_t h0, l0, h1, l1;
                    split2(v[half][4 * ks],     v[half][4 * ks + 1], h0, l0);
                    split2(v[half][4 * ks + 2], v[half][4 * ks + 3], h1, l1);
                    *(uint4*)(g_KF + (((size_t)((bh * 32 + jt) * 8 + jg) * 4 + ks)) * 128 + lp * 4)
                        = make_uint4(h0, h1, l0, l1);
                }
            }
        } else {
#pragma unroll
            for (int half = 0; half < 2; half++) {
                const int s = stile + g + half * 8;
                float* dst = g_V + ((size_t)bh * SEQ + s) * HD;
#pragma unroll
                for (int ng = 0; ng < 8; ng++) {
                    float2 t = { v[half][2 * ng], v[half][2 * ng + 1] };
                    *(float2*)(dst + ng * 8 + 2 * tg) = t;
                }
            }
        }
    }
}

// ---------------------------------------------------------------------------
__global__ __launch_bounds__(256, 2) void out_gemm(
    const float* __restrict__ bias, float* __restrict__ out)
{
    float C[2][8][4];
    gemm_core<32>(g_AF, g_WoF, C);

    const int tid  = threadIdx.x;
    const int warp = tid >> 5;
    const int lane = tid & 31;
    const int wm = warp >> 1, wn = warp & 1;
    const int g = lane >> 2, tg = lane & 3;
    const int m0 = blockIdx.y * 128;
    const int n0 = blockIdx.x * 128;

    float bb[8][2];
#pragma unroll
    for (int ng = 0; ng < 8; ng++) {
        const int n = n0 + wn * 64 + ng * 8 + 2 * tg;
        bb[ng][0] = bias[n];
        bb[ng][1] = bias[n + 1];
    }
#pragma unroll
    for (int mg = 0; mg < 2; mg++) {
#pragma unroll
        for (int half = 0; half < 2; half++) {
            const int m = m0 + wm * 32 + mg * 16 + g + half * 8;
            float* dst = out + (size_t)m * KIN + n0 + wn * 64;
#pragma unroll
            for (int ng = 0; ng < 8; ng++) {
                float2 t = { C[mg][ng][half * 2]     + bb[ng][0],
                             C[mg][ng][half * 2 + 1] + bb[ng][1] };
                *(float2*)(dst + ng * 8 + 2 * tg) = t;
            }
        }
    }
}

// ---------------------------------------------------------------------------
// Attention v3: R14 structure + 3-way accumulator splitting in bc (12
// independent 4-deep HMMA chains per ks2 instead of 4x12-deep) + Estrin
// polynomial (depth 11 -> 5). Everything else identical to R14.
// ---------------------------------------------------------------------------
__global__ __launch_bounds__(128, 2) void attn_tc()
{
    extern __shared__ uint32_t sm[];
    uint32_t* QsB = sm;             // [3][8][4][128]
    uint32_t* VsB = sm + 12288;

    const int tid  = threadIdx.x;
    const int warp = tid >> 5;      // 0..3
    const int lane = tid & 31;
    const int bh   = blockIdx.y;
    const int i0   = blockIdx.x * 128;

    // preload 2 A-frag sets (32 i-rows) from g_QA
    uint4 AhiV[2][4], AloV[2][4];
#pragma unroll
    for (int s = 0; s < 2; s++) {
        const int sg = (i0 >> 4) + warp * 2 + s;
#pragma unroll
        for (int ks = 0; ks < 4; ks++) {
            const uint32_t* src = g_QA + (((size_t)(bh * 128 + sg) * 4 + ks) * 2) * 128 + lane * 4;
            AhiV[s][ks] = *(const uint4*)src;
            AloV[s][ks] = *(const uint4*)(src + 128);
        }
    }

    const u64t K9 = dup2f(-2.0705e-4f);
    const u64t K8 = dup2f(-2.6002e-4f);
    const u64t K7 = dup2f(-6.2160e-4f);
    const u64t K6 = dup2f(-1.52229e-3f);
    const u64t K5 = dup2f(-3.84800e-3f);
    const u64t K4 = dup2f(-1.015873e-2f);
    const u64t K3 = dup2f(-2.8571429e-2f);
    const u64t K2 = dup2f(-8.8888889e-2f);
    const u64t K1 = dup2f(-0.33333333f);
    const u64t K0 = dup2f(-2.0f);
    const u64t CM1 = dup2f(-1.0f);
    const u64t CP1 = dup2f(1.0f);

    auto copy_tile = [&](int jt, int bf) {
        uint32_t* Q = QsB + bf * 4096;
        uint32_t* Vv = VsB + bf * 4096;
#pragma unroll
        for (int t = 0; t < 2; t++) {
            const int gidx = warp * 2 + t;
            const uint32_t* qs = g_KF + ((size_t)((bh * 32 + jt) * 8 + gidx) * 4) * 128 + lane * 4;
            const uint32_t* vs = g_VF + ((size_t)((bh * 32 + jt) * 8 + gidx) * 4) * 128 + lane * 4;
#pragma unroll
            for (int ks = 0; ks < 4; ks++) {
                cp16(&Q[gidx * 512 + ks * 128 + lane * 4],  qs + ks * 128);
                cp16(&Vv[gidx * 512 + ks * 128 + lane * 4], vs + ks * 128);
            }
        }
        CP_COMMIT();
    };

    float o[2][8][4];
#pragma unroll
    for (int s = 0; s < 2; s++)
#pragma unroll
        for (int dg = 0; dg < 8; dg++)
#pragma unroll
            for (int e = 0; e < 4; e++) o[s][dg][e] = 0.0f;
    float den[2][2] = { {0.0f, 0.0f}, {0.0f, 0.0f} };

    copy_tile(0, 0);
    copy_tile(1, 1);

    const int NT = SEQ / 64;   // 32
    for (int t = 0; t < NT; ++t) {
        const int cur = t % 3;
        if (t + 1 < NT) { CP_WAIT1(); } else { CP_WAIT0(); }
        __syncthreads();
        const uint32_t* Q = QsB + cur * 4096;
        const uint32_t* Vv = VsB + cur * 4096;

#pragma unroll
        for (int ks2 = 0; ks2 < 4; ks2++) {
            // --- bc: 12 independent 4-deep accumulator chains ---
            float a1[2][2][4], a2[2][2][4], a3[2][2][4];
#pragma unroll
            for (int s = 0; s < 2; s++)
#pragma unroll
                for (int e = 0; e < 2; e++)
#pragma unroll
                    for (int q = 0; q < 4; q++) {
                        a1[s][e][q] = 0.0f; a2[s][e][q] = 0.0f; a3[s][e][q] = 0.0f;
                    }
#pragma unroll
            for (int ks = 0; ks < 4; ks++) {
                uint4 q0 = *(const uint4*)&Q[(2 * ks2 + 0) * 512 + ks * 128 + lane * 4];
                uint4 q1 = *(const uint4*)&Q[(2 * ks2 + 1) * 512 + ks * 128 + lane * 4];
#pragma unroll
                for (int s = 0; s < 2; s++) {
                    mma_bf16_u4(a1[s][0], AhiV[s][ks], q0.x, q0.y);
                    mma_bf16_u4(a2[s][0], AloV[s][ks], q0.x, q0.y);
                    mma_bf16_u4(a3[s][0], AhiV[s][ks], q0.z, q0.w);
                    mma_bf16_u4(a1[s][1], AhiV[s][ks], q1.x, q1.y);
                    mma_bf16_u4(a2[s][1], AloV[s][ks], q1.x, q1.y);
                    mma_bf16_u4(a3[s][1], AhiV[s][ks], q1.z, q1.w);
                }
            }

            // --- transform (Estrin) + pack w A-frags ---
            uint32_t Whi4[2][4], Wlo4[2][4];
#pragma unroll
            for (int s = 0; s < 2; s++) {
#pragma unroll
                for (int e = 0; e < 2; e++) {
                    float acc[4];
#pragma unroll
                    for (int q = 0; q < 4; q++)
                        acc[q] = (a1[s][e][q] + a2[s][e][q]) + a3[s][e][q];
                    u64t ua = fma2(pk2(acc[0], acc[1]), CM1, CP1);
                    u64t ub = fma2(pk2(acc[2], acc[3]), CM1, CP1);
                    // Estrin
                    u64t ua2 = mul2(ua, ua), ub2 = mul2(ub, ub);
                    u64t ua4 = mul2(ua2, ua2), ub4 = mul2(ub2, ub2);
                    u64t ua8 = mul2(ua4, ua4), ub8 = mul2(ub4, ub4);
                    u64t b0a = fma2(K1, ua, K0), b0b = fma2(K1, ub, K0);
                    u64t b1a = fma2(K3, ua, K2), b1b = fma2(K3, ub, K2);
                    u64t b2a = fma2(K5, ua, K4), b2b = fma2(K5, ub, K4);
                    u64t b3a = fma2(K7, ua, K6), b3b = fma2(K7, ub, K6);
                    u64t b4a = fma2(K9, ua, K8), b4b = fma2(K9, ub, K8);
                    u64t q0a = fma2(b1a, ua2, b0a), q0b = fma2(b1b, ub2, b0b);
                    u64t q1a = fma2(b3a, ua2, b2a), q1b = fma2(b3b, ub2, b2b);
                    u64t r0a = fma2(q1a, ua4, q0a), r0b = fma2(q1b, ub4, q0b);
                    u64t ga = fma2(b4a, ua8, r0a),  gb = fma2(b4b, ub8, r0b);
                    ga = mul2(ga, ua);              gb = mul2(gb, ub);
                    float2 gA = unpk(ga), gB = unpk(gb);
                    float w0 = __expf(gA.x), w1 = __expf(gA.y);
                    float w2 = __expf(gB.x), w3 = __expf(gB.y);
                    den[s][0] += w0 + w1;
                    den[s][1] += w2 + w3;
                    split2(w0, w1, Whi4[s][2 * e + 0], Wlo4[s][2 * e + 0]);
                    split2(w2, w3, Whi4[s][2 * e + 1], Wlo4[s][2 * e + 1]);
                }
            }

            // --- w @ V for js = ks2, both i-sets share the V frag read ---
#pragma unroll
            for (int dg = 0; dg < 8; dg++) {
                uint4 v = *(const uint4*)&Vv[dg * 512 + ks2 * 128 + lane * 4];
#pragma unroll
                for (int s = 0; s < 2; s++) {
                    mma_bf16(o[s][dg], Whi4[s], v.x, v.y);
                    mma_bf16(o[s][dg], Wlo4[s], v.x, v.y);
                    mma_bf16(o[s][dg], Whi4[s], v.z, v.w);
                }
            }
        }

        if (t + 2 < NT) copy_tile(t + 2, (t + 2) % 3);
    }

    // epilogue per i-set
    const int b = bh >> 3, hh = bh & 7;
#pragma unroll
    for (int s = 0; s < 2; s++) {
        float d0 = den[s][0], d1 = den[s][1];
        d0 += __shfl_xor_sync(0xffffffffu, d0, 1);
        d0 += __shfl_xor_sync(0xffffffffu, d0, 2);
        d1 += __shfl_xor_sync(0xffffffffu, d1, 1);
        d1 += __shfl_xor_sync(0xffffffffu, d1, 2);
        const float inv0 = 1.0f / d0;
        const float inv1 = 1.0f / d1;

        const int mgg = b * 128 + (i0 >> 4) + warp * 2 + s;
#pragma unroll
        for (int k = 0; k < 4; k++) {
            uint32_t h4[4], l4[4];
            split2(o[s][2 * k][0] * inv0,     o[s][2 * k][1] * inv0,     h4[0], l4[0]);
            split2(o[s][2 * k][2] * inv1,     o[s][2 * k][3] * inv1,     h4[1], l4[1]);
            split2(o[s][2 * k + 1][0] * inv0, o[s][2 * k + 1][1] * inv0, h4[2], l4[2]);
            split2(o[s][2 * k + 1][2] * inv1, o[s][2 * k + 1][3] * inv1, h4[3], l4[3]);
            const int ksg = hh * 4 + k;
            uint32_t* dst = g_AF + ((size_t)(mgg * 32 + ksg) * 2) * 128 + lane * 4;
            *(uint4*)dst         = make_uint4(h4[0], h4[1], h4[2], h4[3]);
            *(uint4*)(dst + 128) = make_uint4(l4[0], l4[1], l4[2], l4[3]);
        }
    }
}

// ---------------------------------------------------------------------------
extern "C" void kernel_launch(void* const* d_in, const int* in_sizes, int n_in,
                              void* d_out, int out_size)
{
    const float* xr = (const float*)d_in[0];
    const float* xi = (const float*)d_in[1];
    const float* Wq = (const float*)d_in[2];
    const float* bq = (const float*)d_in[3];
    const float* Wk = (const float*)d_in[4];
    const float* bk = (const float*)d_in[5];
    const float* Wv = (const float*)d_in[6];
    const float* bv = (const float*)d_in[7];
    const float* Wo = (const float*)d_in[8];
    const float* bo = (const float*)d_in[9];
    float* out = (float*)d_out;

    const int smem = 98304;
    cudaFuncSetAttribute(proj_qkv, cudaFuncAttributeMaxDynamicSharedMemorySize, smem);
    cudaFuncSetAttribute(out_gemm, cudaFuncAttributeMaxDynamicSharedMemorySize, smem);
    cudaFuncSetAttribute(attn_tc,  cudaFuncAttributeMaxDynamicSharedMemorySize, smem);

    prep_xa<<<dim3(32, 64), 256>>>(xr, xi);
    prep_w_all<<<dim3(64, 8, 4), 256>>>(Wq, Wk, Wv, Wo);

    dim3 gp(DIM / 128, MTOT / 128, 3);       // (4, 32, 3)
    proj_qkv<<<gp, 256, smem>>>(bq, bk, bv);

    repack_v<<<dim3(32, 16), 256>>>();

    dim3 ga(SEQ / 128, BATCH * NH);          // (16, 16) = 256 blocks
    attn_tc<<<ga, 128, smem>>>();

    dim3 go(KIN / 128, MTOT / 128);          // (8, 32)
    out_gemm<<<go, 256, smem>>>(bo, out);
}

// round 17
// speedup vs baseline: 1.0537x; 1.0537x over previous
#include <cuda_runtime.h>
#include <cuda_bf16.h>
#include <math.h>
#include <stdint.h>

#define DIM   512
#define NH    8
#define HD    64
#define SEQ   2048
#define BATCH 2
#define MTOT  (BATCH * SEQ)   // 4096
#define KIN   (2 * DIM)       // 1024

typedef unsigned long long u64t;

// ---- packed f32x2 helpers ----
__device__ __forceinline__ u64t fma2(u64t a, u64t b, u64t c) {
    u64t d; asm("fma.rn.f32x2 %0, %1, %2, %3;" : "=l"(d) : "l"(a), "l"(b), "l"(c));
    return d;
}
__device__ __forceinline__ u64t mul2(u64t a, u64t b) {
    u64t d; asm("mul.rn.f32x2 %0, %1, %2;" : "=l"(d) : "l"(a), "l"(b));
    return d;
}
__device__ __forceinline__ u64t dup2f(float x) {
    u64t r; asm("mov.b64 %0, {%1, %1};" : "=l"(r) : "f"(x));
    return r;
}
__device__ __forceinline__ u64t pk2(float a, float b) {
    u64t r; asm("mov.b64 %0, {%1, %2};" : "=l"(r) : "f"(a), "f"(b));
    return r;
}
__device__ __forceinline__ float2 unpk(u64t v) {
    float lo, hi; asm("mov.b64 {%0, %1}, %2;" : "=f"(lo), "=f"(hi) : "l"(v));
    float2 f; f.x = lo; f.y = hi; return f;
}

// ---- bf16x2 split (bit-trick, rounding identical to __float2bfloat16) ----
__device__ __forceinline__ void split2(float x, float y, uint32_t& hi, uint32_t& lo) {
    uint32_t h;
    asm("cvt.rn.bf16x2.f32 %0, %1, %2;" : "=r"(h) : "f"(y), "f"(x));
    float hx = __uint_as_float(h << 16);
    float hy = __uint_as_float(h & 0xffff0000u);
    float rx = x - hx;
    float ry = y - hy;
    asm("cvt.rn.bf16x2.f32 %0, %1, %2;" : "=r"(lo) : "f"(ry), "f"(rx));
    hi = h;
}

// ---- mma.sync m16n8k16 bf16 ----
__device__ __forceinline__ void mma_bf16(float c[4], const uint32_t a[4],
                                         uint32_t b0, uint32_t b1) {
    asm volatile(
        "mma.sync.aligned.m16n8k16.row.col.f32.bf16.bf16.f32 "
        "{%0,%1,%2,%3}, {%4,%5,%6,%7}, {%8,%9}, {%0,%1,%2,%3};"
        : "+f"(c[0]), "+f"(c[1]), "+f"(c[2]), "+f"(c[3])
        : "r"(a[0]), "r"(a[1]), "r"(a[2]), "r"(a[3]), "r"(b0), "r"(b1));
}
__device__ __forceinline__ void mma_bf16_u4(float c[4], uint4 a,
                                            uint32_t b0, uint32_t b1) {
    uint32_t ar[4] = { a.x, a.y, a.z, a.w };
    mma_bf16(c, ar, b0, b1);
}

// ---- cp.async 16B ----
__device__ __forceinline__ void cp16(void* smem_dst, const void* gsrc) {
    uint32_t s = (uint32_t)__cvta_generic_to_shared(smem_dst);
    asm volatile("cp.async.cg.shared.global [%0], [%1], 16;" :: "r"(s), "l"(gsrc));
}
#define CP_COMMIT() asm volatile("cp.async.commit_group;")
#define CP_WAIT0()  asm volatile("cp.async.wait_group 0;" ::: "memory")
#define CP_WAIT1()  asm volatile("cp.async.wait_group 1;" ::: "memory")

// ---------------------------------------------------------------------------
// Pre-split fragment-order global buffers
// ---------------------------------------------------------------------------
__device__ uint32_t g_XA[256 * 64 * 2 * 128];
__device__ uint32_t g_WqF[64 * 64 * 128];
__device__ uint32_t g_WkF[64 * 64 * 128];
__device__ uint32_t g_WvF[64 * 64 * 128];
__device__ uint32_t g_WoF[128 * 32 * 128];
__device__ uint32_t g_QA[16 * 128 * 4 * 2 * 128];
__device__ uint32_t g_KF[16 * 32 * 8 * 4 * 128];
__device__ uint32_t g_VF[16 * 32 * 8 * 4 * 128];
__device__ float    g_V [16 * SEQ * HD];
__device__ uint32_t g_AF[256 * 32 * 2 * 128];

// ---------------------------------------------------------------------------
// Fused prep: z<4 -> W B-frag split (Wq/Wk/Wv/Wo); z>=4 -> x A-frag split.
// grid(64, 8, 8), 256 thr.
// ---------------------------------------------------------------------------
__global__ __launch_bounds__(256) void prep_all(
    const float* __restrict__ xr, const float* __restrict__ xi,
    const float* __restrict__ Wq, const float* __restrict__ Wk,
    const float* __restrict__ Wv, const float* __restrict__ Wo)
{
    const int lane = threadIdx.x & 31;
    const int warp = threadIdx.x >> 5;
    const int g = lane >> 2, tg = lane & 3;
    const int z = blockIdx.z;

    if (z < 4) {
        // ---- W -> B-frag split (identical math to R14 prep_w_all) ----
        int ng, ks, N, KGC;
        const float* W;
        uint32_t* WF;
        if (z < 3) {
            ng = blockIdx.x;
            ks = blockIdx.y * 8 + warp;
            N = DIM; KGC = 64;
            W  = (z == 0) ? Wq : (z == 1) ? Wk : Wv;
            WF = (z == 0) ? g_WqF : (z == 1) ? g_WkF : g_WvF;
        } else {
            const int id = blockIdx.y * 64 + blockIdx.x;
            ng = id >> 2;
            ks = (id & 3) * 8 + warp;
            N = KIN; KGC = 32;
            W = Wo; WF = g_WoF;
        }
        const int k = ks * 16 + 2 * tg;
        const int n = ng * 8 + g;
        float b0a = W[(size_t)k * N + n];
        float b0b = W[(size_t)(k + 1) * N + n];
        float b1a = W[(size_t)(k + 8) * N + n];
        float b1b = W[(size_t)(k + 9) * N + n];
        uint32_t h0, l0, h1, l1;
        split2(b0a, b0b, h0, l0);
        split2(b1a, b1b, h1, l1);
        *(uint4*)(WF + (size_t)(ng * KGC + ks) * 128 + lane * 4) = make_uint4(h0, h1, l0, l1);
    } else {
        // ---- x -> A-frag split (identical math to R14 prep_xa) ----
        const int id = (z - 4) * 512 + blockIdx.y * 64 + blockIdx.x;   // 0..2047
        const int bxo = id & 31;          // original blockIdx.x (0..31)
        const int kg  = id >> 5;          // original blockIdx.y (0..63)
        const int mg = bxo * 8 + warp;
        const int m = mg * 16 + g;
        const int k = kg * 16 + 2 * tg;
        const float* base = (k < DIM) ? xr : xi;
        const int kk = k & (DIM - 1);
        float2 f00 = *(const float2*)(base + (size_t)m * DIM + kk);
        float2 f01 = *(const float2*)(base + (size_t)m * DIM + kk + 8);
        float2 f10 = *(const float2*)(base + (size_t)(m + 8) * DIM + kk);
        float2 f11 = *(const float2*)(base + (size_t)(m + 8) * DIM + kk + 8);
        uint32_t h[4], l[4];
        split2(f00.x, f00.y, h[0], l[0]);
        split2(f10.x, f10.y, h[1], l[1]);
        split2(f01.x, f01.y, h[2], l[2]);
        split2(f11.x, f11.y, h[3], l[3]);
        uint32_t* dst = g_XA + ((size_t)(mg * 64 + kg) * 2) * 128 + lane * 4;
        *(uint4*)dst         = make_uint4(h[0], h[1], h[2], h[3]);
        *(uint4*)(dst + 128) = make_uint4(l[0], l[1], l[2], l[3]);
    }
}

// ---------------------------------------------------------------------------
// Repack V fp32 -> B-frag split.  grid(32 jt, 16 bh), 256 thr.
// ---------------------------------------------------------------------------
__global__ __launch_bounds__(256) void repack_v()
{
    const int lane = threadIdx.x & 31;
    const int dg = threadIdx.x >> 5;
    const int r = lane >> 2, cq = lane & 3;
    const int jt = blockIdx.x, bh = blockIdx.y;
    const float* Vb = g_V + (size_t)bh * SEQ * HD;
    const int j0 = jt * 64;
#pragma unroll
    for (int js = 0; js < 4; js++) {
        const float* vsrc = Vb + (size_t)(j0 + js * 16 + 2 * cq) * HD + dg * 8 + r;
        float v0 = vsrc[0];
        float v1 = vsrc[HD];
        float v2 = vsrc[8 * HD];
        float v3 = vsrc[9 * HD];
        uint32_t h0, l0, h1, l1;
        split2(v0, v1, h0, l0);
        split2(v2, v3, h1, l1);
        *(uint4*)(g_VF + ((size_t)((bh * 32 + jt) * 8 + dg) * 4 + js) * 128 + lane * 4)
            = make_uint4(h0, h1, l0, l1);
    }
}

// ---------------------------------------------------------------------------
// GEMM core: 3-stage cp.async pipeline (R13/R14 known-good).
// ---------------------------------------------------------------------------
template<int KGC>
__device__ __forceinline__ void gemm_core(
    const uint32_t* __restrict__ XA, const uint32_t* __restrict__ WF,
    float C[2][8][4])
{
    extern __shared__ uint32_t sm[];
    uint32_t* AsmB = sm;             // [3][8][2][256]
    uint32_t* BsmB = sm + 12288;     // [3][16][2][128]

    const int tid  = threadIdx.x;
    const int warp = tid >> 5;
    const int lane = tid & 31;
    const int wm = warp >> 1, wn = warp & 1;
    const int m0 = blockIdx.y * 128;
    const int n0 = blockIdx.x * 128;
    const int mgA = (m0 >> 4) + warp;
    const int ngB = (n0 >> 3);

    auto copy_chunk = [&](int ch, int bf) {
        const int kg0 = ch * 2;
        uint32_t* A = AsmB + bf * 4096;
        uint32_t* B = BsmB + bf * 4096;
#pragma unroll
        for (int t = 0; t < 2; t++) {
            const uint32_t* src = XA + ((size_t)(mgA * KGC + kg0 + t) * 2) * 128 + lane * 4;
            cp16(&A[warp * 512 + t * 256 + lane * 4], src);
            cp16(&A[warp * 512 + t * 256 + 128 + lane * 4], src + 128);
        }
#pragma unroll
        for (int t = 0; t < 4; t++) {
            const int ngl = warp * 2 + (t >> 1), ks = t & 1;
            cp16(&B[ngl * 256 + ks * 128 + lane * 4],
                 WF + (size_t)((ngB + ngl) * KGC + kg0 + ks) * 128 + lane * 4);
        }
        CP_COMMIT();
    };

#pragma unroll
    for (int mg = 0; mg < 2; mg++)
#pragma unroll
        for (int ng = 0; ng < 8; ng++)
#pragma unroll
            for (int e = 0; e < 4; e++) C[mg][ng][e] = 0.0f;

    const int NCH = KGC / 2;
    copy_chunk(0, 0);
    copy_chunk(1, 1);

    for (int ch = 0; ch < NCH; ++ch) {
        const int cur = ch % 3;
        if (ch + 1 < NCH) { CP_WAIT1(); } else { CP_WAIT0(); }
        __syncthreads();
        const uint32_t* A = AsmB + cur * 4096;
        const uint32_t* B = BsmB + cur * 4096;
#pragma unroll
        for (int ks = 0; ks < 2; ks++) {
            uint4 a0h = *(const uint4*)&A[(wm * 2 + 0) * 512 + ks * 256 + lane * 4];
            uint4 a0l = *(const uint4*)&A[(wm * 2 + 0) * 512 + ks * 256 + 128 + lane * 4];
            uint4 a1h = *(const uint4*)&A[(wm * 2 + 1) * 512 + ks * 256 + lane * 4];
            uint4 a1l = *(const uint4*)&A[(wm * 2 + 1) * 512 + ks * 256 + 128 + lane * 4];
#pragma unroll
            for (int ng = 0; ng < 8; ng++) {
                uint4 b = *(const uint4*)&B[(wn * 8 + ng) * 256 + ks * 128 + lane * 4];
                mma_bf16_u4(C[0][ng], a0h, b.x, b.y);
                mma_bf16_u4(C[0][ng], a0l, b.x, b.y);
                mma_bf16_u4(C[0][ng], a0h, b.z, b.w);
                mma_bf16_u4(C[1][ng], a1h, b.x, b.y);
                mma_bf16_u4(C[1][ng], a1l, b.x, b.y);
                mma_bf16_u4(C[1][ng], a1h, b.z, b.w);
            }
        }
        if (ch + 2 < NCH) copy_chunk(ch + 2, (ch + 2) % 3);
    }
}

// ---------------------------------------------------------------------------
// Fused Q/K/V projection (R14 known-good).
// ---------------------------------------------------------------------------
__global__ __launch_bounds__(256, 2) void proj_qkv(
    const float* __restrict__ bq, const float* __restrict__ bk,
    const float* __restrict__ bv)
{
    const int z = blockIdx.z;
    const uint32_t* WF = (z == 0) ? g_WqF : (z == 1) ? g_WkF : g_WvF;
    const float* bias = (z == 0) ? bq : (z == 1) ? bk : bv;

    float C[2][8][4];
    gemm_core<64>(g_XA, WF, C);

    const int tid  = threadIdx.x;
    const int warp = tid >> 5;
    const int lane = tid & 31;
    const int wm = warp >> 1, wn = warp & 1;
    const int g = lane >> 2, tg = lane & 3;
    const int m0 = blockIdx.y * 128;
    const int n0 = blockIdx.x * 128;
    const int h = (n0 + wn * 64) >> 6;

    float bb[8][2];
#pragma unroll
    for (int ng = 0; ng < 8; ng++) {
        const int n = n0 + wn * 64 + ng * 8 + 2 * tg;
        bb[ng][0] = bias[n];
        bb[ng][1] = bias[n + 1];
    }

#pragma unroll
    for (int mg = 0; mg < 2; mg++) {
        const int mtile = m0 + wm * 32 + mg * 16;
        const int b = mtile >> 11;
        const int stile = mtile & (SEQ - 1);
        const int bh = b * NH + h;
        float v[2][16];
#pragma unroll
        for (int half = 0; half < 2; half++) {
#pragma unroll
            for (int ng = 0; ng < 8; ng++) {
                v[half][2 * ng]     = C[mg][ng][half * 2]     + bb[ng][0];
                v[half][2 * ng + 1] = C[mg][ng][half * 2 + 1] + bb[ng][1];
            }
            if (z < 2) {
                float mx = v[half][0];
#pragma unroll
                for (int e = 1; e < 16; e++) mx = fmaxf(mx, v[half][e]);
                mx = fmaxf(mx, __shfl_xor_sync(0xffffffffu, mx, 1));
                mx = fmaxf(mx, __shfl_xor_sync(0xffffffffu, mx, 2));
                float sum = 0.0f;
#pragma unroll
                for (int e = 0; e < 16; e++) { v[half][e] = __expf(v[half][e] - mx); sum += v[half][e]; }
                sum += __shfl_xor_sync(0xffffffffu, sum, 1);
                sum += __shfl_xor_sync(0xffffffffu, sum, 2);
                const float inv = 1.0f / sum;
#pragma unroll
                for (int e = 0; e < 16; e++) v[half][e] = sqrtf(v[half][e] * inv);
            }
        }

        if (z == 0) {
            const int sg = stile >> 4;
#pragma unroll
            for (int ks = 0; ks < 4; ks++) {
                uint32_t h4[4], l4[4];
                split2(v[0][4 * ks],     v[0][4 * ks + 1], h4[0], l4[0]);
                split2(v[1][4 * ks],     v[1][4 * ks + 1], h4[1], l4[1]);
                split2(v[0][4 * ks + 2], v[0][4 * ks + 3], h4[2], l4[2]);
                split2(v[1][4 * ks + 2], v[1][4 * ks + 3], h4[3], l4[3]);
                uint32_t* dst = g_QA + (((size_t)(bh * 128 + sg) * 4 + ks) * 2) * 128 + lane * 4;
                *(uint4*)dst         = make_uint4(h4[0], h4[1], h4[2], h4[3]);
                *(uint4*)(dst + 128) = make_uint4(l4[0], l4[1], l4[2], l4[3]);
            }
        } else if (z == 1) {
#pragma unroll
            for (int half = 0; half < 2; half++) {
                const int s = stile + g + half * 8;
                const int jt = s >> 6, jg = (s >> 3) & 7;
                const int lp = (s & 7) * 4 + tg;
#pragma unroll
                for (int ks = 0; ks < 4; ks++) {
                    uint32_t h0, l0, h1, l1;
                    split2(v[half][4 * ks],     v[half][4 * ks + 1], h0, l0);
                    split2(v[half][4 * ks + 2], v[half][4 * ks + 3], h1, l1);
                    *(uint4*)(g_KF + (((size_t)((bh * 32 + jt) * 8 + jg) * 4 + ks)) * 128 + lp * 4)
                        = make_uint4(h0, h1, l0, l1);
                }
            }
        } else {
#pragma unroll
            for (int half = 0; half < 2; half++) {
                const int s = stile + g + half * 8;
                float* dst = g_V + ((size_t)bh * SEQ + s) * HD;
#pragma unroll
                for (int ng = 0; ng < 8; ng++) {
                    float2 t = { v[half][2 * ng], v[half][2 * ng + 1] };
                    *(float2*)(dst + ng * 8 + 2 * tg) = t;
                }
            }
        }
    }
}

// ---------------------------------------------------------------------------
__global__ __launch_bounds__(256, 2) void out_gemm(
    const float* __restrict__ bias, float* __restrict__ out)
{
    float C[2][8][4];
    gemm_core<32>(g_AF, g_WoF, C);

    const int tid  = threadIdx.x;
    const int warp = tid >> 5;
    const int lane = tid & 31;
    const int wm = warp >> 1, wn = warp & 1;
    const int g = lane >> 2, tg = lane & 3;
    const int m0 = blockIdx.y * 128;
    const int n0 = blockIdx.x * 128;

    float bb[8][2];
#pragma unroll
    for (int ng = 0; ng < 8; ng++) {
        const int n = n0 + wn * 64 + ng * 8 + 2 * tg;
        bb[ng][0] = bias[n];
        bb[ng][1] = bias[n + 1];
    }
#pragma unroll
    for (int mg = 0; mg < 2; mg++) {
#pragma unroll
        for (int half = 0; half < 2; half++) {
            const int m = m0 + wm * 32 + mg * 16 + g + half * 8;
            float* dst = out + (size_t)m * KIN + n0 + wn * 64;
#pragma unroll
            for (int ng = 0; ng < 8; ng++) {
                float2 t = { C[mg][ng][half * 2]     + bb[ng][0],
                             C[mg][ng][half * 2 + 1] + bb[ng][1] };
                *(float2*)(dst + ng * 8 + 2 * tg) = t;
            }
        }
    }
}

// ---------------------------------------------------------------------------
// Attention (R14 known-good, bit-exact): 128 threads (4 warps), each warp
// owns 32 i-rows (2 A-frag sets), 3-stage cp.async pipeline, transform
// interleaved with w@V per ks-group.
// ---------------------------------------------------------------------------
__global__ __launch_bounds__(128, 2) void attn_tc()
{
    extern __shared__ uint32_t sm[];
    uint32_t* QsB = sm;             // [3][8][4][128]
    uint32_t* VsB = sm + 12288;

    const int tid  = threadIdx.x;
    const int warp = tid >> 5;      // 0..3
    const int lane = tid & 31;
    const int bh   = blockIdx.y;
    const int i0   = blockIdx.x * 128;

    uint4 AhiV[2][4], AloV[2][4];
#pragma unroll
    for (int s = 0; s < 2; s++) {
        const int sg = (i0 >> 4) + warp * 2 + s;
#pragma unroll
        for (int ks = 0; ks < 4; ks++) {
            const uint32_t* src = g_QA + (((size_t)(bh * 128 + sg) * 4 + ks) * 2) * 128 + lane * 4;
            AhiV[s][ks] = *(const uint4*)src;
            AloV[s][ks] = *(const uint4*)(src + 128);
        }
    }

    const u64t K9 = dup2f(-2.0705e-4f);
    const u64t K8 = dup2f(-2.6002e-4f);
    const u64t K7 = dup2f(-6.2160e-4f);
    const u64t K6 = dup2f(-1.52229e-3f);
    const u64t K5 = dup2f(-3.84800e-3f);
    const u64t K4 = dup2f(-1.015873e-2f);
    const u64t K3 = dup2f(-2.8571429e-2f);
    const u64t K2 = dup2f(-8.8888889e-2f);
    const u64t K1 = dup2f(-0.33333333f);
    const u64t K0 = dup2f(-2.0f);
    const u64t CM1 = dup2f(-1.0f);
    const u64t CP1 = dup2f(1.0f);

    auto copy_tile = [&](int jt, int bf) {
        uint32_t* Q = QsB + bf * 4096;
        uint32_t* Vv = VsB + bf * 4096;
#pragma unroll
        for (int t = 0; t < 2; t++) {
            const int gidx = warp * 2 + t;
            const uint32_t* qs = g_KF + ((size_t)((bh * 32 + jt) * 8 + gidx) * 4) * 128 + lane * 4;
            const uint32_t* vs = g_VF + ((size_t)((bh * 32 + jt) * 8 + gidx) * 4) * 128 + lane * 4;
#pragma unroll
            for (int ks = 0; ks < 4; ks++) {
                cp16(&Q[gidx * 512 + ks * 128 + lane * 4],  qs + ks * 128);
                cp16(&Vv[gidx * 512 + ks * 128 + lane * 4], vs + ks * 128);
            }
        }
        CP_COMMIT();
    };

    float o[2][8][4];
#pragma unroll
    for (int s = 0; s < 2; s++)
#pragma unroll
        for (int dg = 0; dg < 8; dg++)
#pragma unroll
            for (int e = 0; e < 4; e++) o[s][dg][e] = 0.0f;
    float den[2][2] = { {0.0f, 0.0f}, {0.0f, 0.0f} };

    copy_tile(0, 0);
    copy_tile(1, 1);

    const int NT = SEQ / 64;   // 32
    for (int t = 0; t < NT; ++t) {
        const int cur = t % 3;
        if (t + 1 < NT) { CP_WAIT1(); } else { CP_WAIT0(); }
        __syncthreads();
        const uint32_t* Q = QsB + cur * 4096;
        const uint32_t* Vv = VsB + cur * 4096;

#pragma unroll
        for (int ks2 = 0; ks2 < 4; ks2++) {
            uint32_t Whi4[2][4], Wlo4[2][4];
#pragma unroll
            for (int s = 0; s < 2; s++) {
#pragma unroll
                for (int e = 0; e < 2; e++) {
                    const int jg = 2 * ks2 + e;
                    float acc[4] = { 0.0f, 0.0f, 0.0f, 0.0f };
#pragma unroll
                    for (int ks = 0; ks < 4; ks++) {
                        uint4 q = *(const uint4*)&Q[jg * 512 + ks * 128 + lane * 4];
                        mma_bf16_u4(acc, AhiV[s][ks], q.x, q.y);
                        mma_bf16_u4(acc, AloV[s][ks], q.x, q.y);
                        mma_bf16_u4(acc, AhiV[s][ks], q.z, q.w);
                    }
                    u64t ua = fma2(pk2(acc[0], acc[1]), CM1, CP1);
                    u64t ub = fma2(pk2(acc[2], acc[3]), CM1, CP1);
                    u64t ga = K9, gb = K9;
                    ga = fma2(ga, ua, K8);  gb = fma2(gb, ub, K8);
                    ga = fma2(ga, ua, K7);  gb = fma2(gb, ub, K7);
                    ga = fma2(ga, ua, K6);  gb = fma2(gb, ub, K6);
                    ga = fma2(ga, ua, K5);  gb = fma2(gb, ub, K5);
                    ga = fma2(ga, ua, K4);  gb = fma2(gb, ub, K4);
                    ga = fma2(ga, ua, K3);  gb = fma2(gb, ub, K3);
                    ga = fma2(ga, ua, K2);  gb = fma2(gb, ub, K2);
                    ga = fma2(ga, ua, K1);  gb = fma2(gb, ub, K1);
                    ga = fma2(ga, ua, K0);  gb = fma2(gb, ub, K0);
                    ga = mul2(ga, ua);      gb = mul2(gb, ub);
                    float2 gA = unpk(ga), gB = unpk(gb);
                    float w0 = __expf(gA.x), w1 = __expf(gA.y);
                    float w2 = __expf(gB.x), w3 = __expf(gB.y);
                    den[s][0] += w0 + w1;
                    den[s][1] += w2 + w3;
                    split2(w0, w1, Whi4[s][2 * e + 0], Wlo4[s][2 * e + 0]);
                    split2(w2, w3, Whi4[s][2 * e + 1], Wlo4[s][2 * e + 1]);
                }
            }
#pragma unroll
            for (int dg = 0; dg < 8; dg++) {
                uint4 v = *(const uint4*)&Vv[dg * 512 + ks2 * 128 + lane * 4];
#pragma unroll
                for (int s = 0; s < 2; s++) {
                    mma_bf16(o[s][dg], Whi4[s], v.x, v.y);
                    mma_bf16(o[s][dg], Wlo4[s], v.x, v.y);
                    mma_bf16(o[s][dg], Whi4[s], v.z, v.w);
                }
            }
        }

        if (t + 2 < NT) copy_tile(t + 2, (t + 2) % 3);
    }

    const int b = bh >> 3, hh = bh & 7;
#pragma unroll
    for (int s = 0; s < 2; s++) {
        float d0 = den[s][0], d1 = den[s][1];
        d0 += __shfl_xor_sync(0xffffffffu, d0, 1);
        d0 += __shfl_xor_sync(0xffffffffu, d0, 2);
        d1 += __shfl_xor_sync(0xffffffffu, d1, 1);
        d1 += __shfl_xor_sync(0xffffffffu, d1, 2);
        const float inv0 = 1.0f / d0;
        const float inv1 = 1.0f / d1;

        const int mgg = b * 128 + (i0 >> 4) + warp * 2 + s;
#pragma unroll
        for (int k = 0; k < 4; k++) {
            uint32_t h4[4], l4[4];
            split2(o[s][2 * k][0] * inv0,     o[s][2 * k][1] * inv0,     h4[0], l4[0]);
            split2(o[s][2 * k][2] * inv1,     o[s][2 * k][3] * inv1,     h4[1], l4[1]);
            split2(o[s][2 * k + 1][0] * inv0, o[s][2 * k + 1][1] * inv0, h4[2], l4[2]);
            split2(o[s][2 * k + 1][2] * inv1, o[s][2 * k + 1][3] * inv1, h4[3], l4[3]);
            const int ksg = hh * 4 + k;
            uint32_t* dst = g_AF + ((size_t)(mgg * 32 + ksg) * 2) * 128 + lane * 4;
            *(uint4*)dst         = make_uint4(h4[0], h4[1], h4[2], h4[3]);
            *(uint4*)(dst + 128) = make_uint4(l4[0], l4[1], l4[2], l4[3]);
        }
    }
}

// ---------------------------------------------------------------------------
extern "C" void kernel_launch(void* const* d_in, const int* in_sizes, int n_in,
                              void* d_out, int out_size)
{
    const float* xr = (const float*)d_in[0];
    const float* xi = (const float*)d_in[1];
    const float* Wq = (const float*)d_in[2];
    const float* bq = (const float*)d_in[3];
    const float* Wk = (const float*)d_in[4];
    const float* bk = (const float*)d_in[5];
    const float* Wv = (const float*)d_in[6];
    const float* bv = (const float*)d_in[7];
    const float* Wo = (const float*)d_in[8];
    const float* bo = (const float*)d_in[9];
    float* out = (float*)d_out;

    const int smem = 98304;
    cudaFuncSetAttribute(proj_qkv, cudaFuncAttributeMaxDynamicSharedMemorySize, smem);
    cudaFuncSetAttribute(out_gemm, cudaFuncAttributeMaxDynamicSharedMemorySize, smem);
    cudaFuncSetAttribute(attn_tc,  cudaFuncAttributeMaxDynamicSharedMemorySize, smem);

    prep_all<<<dim3(64, 8, 8), 256>>>(xr, xi, Wq, Wk, Wv, Wo);

    dim3 gp(DIM / 128, MTOT / 128, 3);       // (4, 32, 3)
    proj_qkv<<<gp, 256, smem>>>(bq, bk, bv);

    repack_v<<<dim3(32, 16), 256>>>();

    dim3 ga(SEQ / 128, BATCH * NH);          // (16, 16) = 256 blocks
    attn_tc<<<ga, 128, smem>>>();

    dim3 go(KIN / 128, MTOT / 128);          // (8, 32)
    out_gemm<<<go, 256, smem>>>(bo, out);
}